// round 10
// baseline (speedup 1.0000x reference)
#include <cuda_runtime.h>
#include <math.h>
#include <stdint.h>

#define S_LEN 2048
#define B_SZ  64
#define E_SZ  256
#define H_SZ  256

// Scratch for x_proj: [S, B, H] fp32 = 134 MB
__device__ float g_xproj[(size_t)S_LEN * B_SZ * H_SZ];

typedef unsigned long long ull;

// ---- packed f32x2 helpers ---------------------------------------------------
__device__ __forceinline__ ull fma2(ull a, ull b, ull c) {
    ull d;
    asm("fma.rn.f32x2 %0, %1, %2, %3;" : "=l"(d) : "l"(a), "l"(b), "l"(c));
    return d;
}
__device__ __forceinline__ ull add2(ull a, ull b) {
    ull d;
    asm("add.rn.f32x2 %0, %1, %2;" : "=l"(d) : "l"(a), "l"(b));
    return d;
}
__device__ __forceinline__ ull pack2(float lo, float hi) {
    ull d;
    asm("mov.b64 %0, {%1, %2};" : "=l"(d) : "f"(lo), "f"(hi));
    return d;
}
__device__ __forceinline__ void unpack2(ull v, float& lo, float& hi) {
    asm("mov.b64 {%0, %1}, %2;" : "=f"(lo), "=f"(hi) : "l"(v));
}

// fast tanh: tanh(x) = 1 - 2/(exp(2x)+1), via MUFU.EX2 + MUFU.RCP (~1e-6 err)
__device__ __forceinline__ float fast_tanh(float x) {
    float u, r;
    asm("ex2.approx.f32 %0, %1;" : "=f"(u) : "f"(x * 2.885390082f));
    asm("rcp.approx.f32 %0, %1;" : "=f"(r) : "f"(u + 1.0f));
    return fmaf(-2.0f, r, 1.0f);
}

// ---------------------------------------------------------------------------
// Kernel 1: x_proj = sentence @ W_ih + b  (R4 version — measured ~393us)
// ---------------------------------------------------------------------------
__global__ __launch_bounds__(256) void xproj_kernel(
    const float* __restrict__ sent,
    const float* __restrict__ Wih,
    const float* __restrict__ bias)
{
    __shared__ float xs[8][256];
    __shared__ float part[4][8][256];

    const int t  = threadIdx.x;
    const int m0 = blockIdx.x * 8;

    {
        const float4* srow = (const float4*)(sent + (size_t)m0 * 256);
        float4* xs4 = (float4*)&xs[0][0];
        #pragma unroll
        for (int i = 0; i < 2; i++)
            xs4[t + i * 256] = srow[t + i * 256];
    }
    __syncthreads();

    const int jg = t & 63;
    const int ks = t >> 6;
    const float4* W4 = (const float4*)Wih;

    float4 acc[8];
    #pragma unroll
    for (int r = 0; r < 8; r++) acc[r] = make_float4(0.f, 0.f, 0.f, 0.f);

    #pragma unroll 8
    for (int i = 0; i < 64; i++) {
        const int k = ks * 64 + i;
        const float4 w = W4[k * 64 + jg];
        #pragma unroll
        for (int r = 0; r < 8; r++) {
            const float xv = xs[r][k];
            acc[r].x += xv * w.x;
            acc[r].y += xv * w.y;
            acc[r].z += xv * w.z;
            acc[r].w += xv * w.w;
        }
    }

    #pragma unroll
    for (int r = 0; r < 8; r++)
        *(float4*)&part[ks][r][4 * jg] = acc[r];
    __syncthreads();

    const float bj = bias[t];
    #pragma unroll
    for (int r = 0; r < 8; r++) {
        const float v = part[0][r][t] + part[1][r][t] +
                        part[2][r][t] + part[3][r][t] + bj;
        g_xproj[(size_t)(m0 + r) * 256 + t] = v;
    }
}

// ---------------------------------------------------------------------------
// Kernel 2: the scan. 64 working CTAs (1 batch row), 512 threads.
// Thread t = (j = t>>1, half = t&1): owns column j, k-range half*128..+128.
// Dot product computed ALONE per thread (64 fma2) -> reduction is ONE
// shfl.xor(1). W per thread = 64 f32x2 pairs: 48 in regs (96 regs, leaving
// headroom for load pipelining), 16 in SMEM (64 KB, conflict-free layout).
// h: packed (h2i, h2i+1) pairs, double-buffered, +pad so the two halves'
// broadcast reads hit different banks. ONE __syncthreads per step.
// Grid padded to 148 CTAs (extras exit) to dodge low-grid issue throttle.
// ---------------------------------------------------------------------------
#define M_REG  48            // W pairs in registers per thread
#define M_SMEM 16            // W pairs in SMEM per thread (8 ulonglong2)
#define HSTR   66            // ull stride per 64-pair half-region (2 pad)

__global__ __launch_bounds__(512, 1) void scan_kernel(
    const float* __restrict__ Whh,    // [256,256] row-major (k, j)
    const float* __restrict__ h0,     // [64,256]
    float* __restrict__ out)          // [64,256]
{
    extern __shared__ ull smem[];
    // sWp: [M_SMEM/2][512] ulonglong2 = 64 KB  (entry i2,t = pairs 48+2i2,+1)
    // hbuf: [2 bufs][2 halves][HSTR] ull = 2112 B
    ulonglong2* sWp  = (ulonglong2*)smem;
    ull*        hbuf = smem + (size_t)(M_SMEM / 2) * 512 * 2;
    float*      hbuf_f = (float*)hbuf;

    const int t    = threadIdx.x;
    const int b    = blockIdx.x;
    if (b >= B_SZ) return;            // grid padded to 148
    const int j    = t >> 1;          // column 0..255
    const int half = t & 1;           // k-half

    // ---- one-time: register W pairs m = 0..47 (k = 128*half + 2m, +1) ----
    ull wr[M_REG];
    #pragma unroll
    for (int m = 0; m < M_REG; m++) {
        const int k = 128 * half + 2 * m;
        wr[m] = pack2(Whh[(size_t)k * 256 + j], Whh[(size_t)(k + 1) * 256 + j]);
    }
    // ---- one-time: SMEM W pairs m = 48..63 ----
    #pragma unroll
    for (int i2 = 0; i2 < M_SMEM / 2; i2++) {
        const int m = M_REG + 2 * i2;
        const int k = 128 * half + 2 * m;
        ulonglong2 wv;
        wv.x = pack2(Whh[(size_t)k * 256 + j],       Whh[(size_t)(k + 1) * 256 + j]);
        wv.y = pack2(Whh[(size_t)(k + 2) * 256 + j], Whh[(size_t)(k + 3) * 256 + j]);
        sWp[i2 * 512 + t] = wv;
    }

    // ---- init h buffer 0: pair p of region hh = (h[128hh+2p], h[128hh+2p+1])
    if (t < 128) {
        const int hh = t >> 6;
        const int p  = t & 63;
        hbuf[hh * HSTR + p] =
            pack2(h0[(size_t)b * 256 + 128 * hh + 2 * p],
                  h0[(size_t)b * 256 + 128 * hh + 2 * p + 1]);
    }
    __syncthreads();

    float xcur = g_xproj[((size_t)0 * B_SZ + b) * 256 + j];
    float hlast = 0.f;

    // this thread's h read base (ulonglong2 index): buf*66 + half*33
    for (int s = 0; s < S_LEN; s++) {
        const int cb = s & 1;
        const int nb = cb ^ 1;

        float xnext;
        {
            const int sn = (s + 1 < S_LEN) ? s + 1 : s;
            xnext = g_xproj[((size_t)sn * B_SZ + b) * 256 + j];
        }

        const ulonglong2* hb2 =
            (const ulonglong2*)(hbuf + cb * (2 * HSTR) + half * HSTR);

        ull a0 = 0, a1 = 0;

        // register part: pairs m = 2i, 2i+1 for i = 0..23
        #pragma unroll
        for (int i = 0; i < M_REG / 2; i++) {
            const ulonglong2 hv = hb2[i];
            a0 = fma2(wr[2 * i],     hv.x, a0);
            a1 = fma2(wr[2 * i + 1], hv.y, a1);
        }
        // smem part: i2 = 0..7 (pairs 48+2i2, 49+2i2)
        #pragma unroll
        for (int i2 = 0; i2 < M_SMEM / 2; i2++) {
            const ulonglong2 hv = hb2[M_REG / 2 + i2];
            const ulonglong2 wv = sWp[i2 * 512 + t];
            a0 = fma2(wv.x, hv.x, a0);
            a1 = fma2(wv.y, hv.y, a1);
        }

        // ---- finalize: horizontal sum + cross-half shfl ----
        float lo, hi;
        unpack2(add2(a0, a1), lo, hi);
        float v = lo + hi;
        v += __shfl_xor_sync(0xffffffffu, v, 1);   // add other k-half

        if (half == 0) {
            const float h = fast_tanh(v + xcur);
            hlast = h;
            // h[j] lives in region (j>=128), pair (j&127)>>1, element j&1
            hbuf_f[(nb * 2 + (j >> 7)) * (HSTR * 2) + (j & 127)] = h;
        }
        xcur = xnext;
        __syncthreads();    // ONE barrier: new buffer complete
    }

    if (half == 0)
        out[(size_t)b * 256 + j] = hlast;
}

// ---------------------------------------------------------------------------
extern "C" void kernel_launch(void* const* d_in, const int* in_sizes, int n_in,
                              void* d_out, int out_size)
{
    const float* sentence = (const float*)d_in[0];
    const float* h0       = (const float*)d_in[1];
    const float* W_ih     = (const float*)d_in[2];
    const float* W_hh     = (const float*)d_in[3];
    const float* bias     = (const float*)d_in[4];
    float* out = (float*)d_out;

    (void)in_sizes; (void)n_in; (void)out_size;

    xproj_kernel<<<(S_LEN * B_SZ) / 8, 256>>>(sentence, W_ih, bias);

    // smem: sWp 64KB + hbuf 2112B
    const int smem_bytes = (M_SMEM / 2) * 512 * 16 + 2 * 2 * HSTR * 8;
    cudaFuncSetAttribute(scan_kernel,
                         cudaFuncAttributeMaxDynamicSharedMemorySize,
                         smem_bytes);
    scan_kernel<<<148, 512, smem_bytes>>>(W_hh, h0, out);
}

// round 11
// speedup vs baseline: 1.2838x; 1.2838x over previous
#include <cuda_runtime.h>
#include <math.h>
#include <stdint.h>

#define S_LEN 2048
#define B_SZ  64
#define E_SZ  256
#define H_SZ  256
#define NWORK 84          // producer CTAs (64 + 84 = 148 = full chip, 1 CTA/SM)

// Scratch for x_proj: [S, B, H] fp32 = 134 MB
__device__ float g_xproj[(size_t)S_LEN * B_SZ * H_SZ];
// Per-step completion flags (zeroed by zero_flags kernel each call)
__device__ int g_flag[S_LEN];

typedef unsigned long long ull;

// ---- packed f32x2 helpers ---------------------------------------------------
__device__ __forceinline__ ull fma2(ull a, ull b, ull c) {
    ull d;
    asm("fma.rn.f32x2 %0, %1, %2, %3;" : "=l"(d) : "l"(a), "l"(b), "l"(c));
    return d;
}
__device__ __forceinline__ ull add2(ull a, ull b) {
    ull d;
    asm("add.rn.f32x2 %0, %1, %2;" : "=l"(d) : "l"(a), "l"(b));
    return d;
}
__device__ __forceinline__ ull pack2(float lo, float hi) {
    ull d;
    asm("mov.b64 %0, {%1, %2};" : "=l"(d) : "f"(lo), "f"(hi));
    return d;
}
__device__ __forceinline__ void unpack2(ull v, float& lo, float& hi) {
    asm("mov.b64 {%0, %1}, %2;" : "=f"(lo), "=f"(hi) : "l"(v));
}

// ---- release/acquire flag ops ----------------------------------------------
__device__ __forceinline__ int ld_acquire(const int* p) {
    int v;
    asm volatile("ld.acquire.gpu.global.b32 %0, [%1];" : "=r"(v) : "l"(p) : "memory");
    return v;
}
__device__ __forceinline__ void st_release(int* p, int v) {
    asm volatile("st.release.gpu.global.b32 [%0], %1;" :: "l"(p), "r"(v) : "memory");
}

// ---------------------------------------------------------------------------
// zero_flags: reset per-step flags (runs before fused kernel, same stream)
// ---------------------------------------------------------------------------
__global__ void zero_flags() {
    const int i = blockIdx.x * blockDim.x + threadIdx.x;
    if (i < S_LEN) g_flag[i] = 0;
}

// ---------------------------------------------------------------------------
// Fused kernel, grid 148 x 512 threads (all resident in wave 1):
//   blockIdx <  64 : SCAN CTA, batch row b = blockIdx   (exact R4 structure)
//   blockIdx >= 64 : WORKER CTA w, computes x_proj steps s = w, w+84, ...
//                    into g_xproj and publishes g_flag[s] (release).
// Scan gates its x prefetch on ld.acquire(g_flag[s+1]); flag is loaded at
// step top and only checked after the reduce, so the poll is off the
// critical path in the steady state (producers run 2.3x ahead).
// ---------------------------------------------------------------------------
#define K_REG  20
#define K_SMEM 12

__global__ __launch_bounds__(512, 1) void fused_kernel(
    const float* __restrict__ sent,   // [S*B, 256]
    const float* __restrict__ Wih,    // [256,256]
    const float* __restrict__ bias,   // [256]
    const float* __restrict__ Whh,    // [256,256]
    const float* __restrict__ h0,     // [64,256]
    float* __restrict__ out)          // [64,256]
{
    extern __shared__ ull smem[];
    const int t = threadIdx.x;

    if (blockIdx.x < B_SZ) {
        // =================== SCAN (R4 structure, unchanged math) ===========
        // layout: sW [8][12][64] ulonglong2 (96 KB), part [8][128] ull (8 KB),
        //         hbuf [256] ull (2 KB)
        ulonglong2* sW   = (ulonglong2*)smem;
        ull*        part = (ull*)(smem + 8 * 12 * 64 * 2);
        ull*        hbuf = part + 8 * 128;

        const int b  = blockIdx.x;
        const int ks = t >> 6;        // 0..7
        const int jq = t & 63;        // 4 columns: 4jq .. 4jq+3
        const int kbase = ks * 32;

        // register-resident W slice (20 k's x 4 cols)
        ull wr[2 * K_REG];
        #pragma unroll
        for (int i = 0; i < K_REG; i++) {
            const int k = kbase + i;
            const ulonglong2 wv = *(const ulonglong2*)&Whh[(size_t)k * 256 + 4 * jq];
            wr[2 * i]     = wv.x;
            wr[2 * i + 1] = wv.y;
        }

        // SMEM W slice (12 k's per ks-group)
        for (int idx = t; idx < 8 * K_SMEM * 64; idx += 512) {
            const int fjq = idx & 63;
            const int fm  = (idx >> 6) % K_SMEM;
            const int fks = idx / (K_SMEM * 64);
            const int k   = fks * 32 + K_REG + fm;
            sW[(fks * K_SMEM + fm) * 64 + fjq] =
                *(const ulonglong2*)&Whh[(size_t)k * 256 + 4 * fjq];
        }

        // init h (replicated pairs)
        if (t < 256) {
            const float h = h0[(size_t)b * 256 + t];
            hbuf[t] = pack2(h, h);
        }
        __syncthreads();

        // prologue: wait for step 0's x, then load it
        ull xcur = 0;
        if (t < 128) {
            int f0 = ld_acquire(&g_flag[0]);
            while (f0 == 0) { __nanosleep(64); f0 = ld_acquire(&g_flag[0]); }
            xcur = *(const ull*)&g_xproj[((size_t)0 * B_SZ + b) * 256 + 2 * t];
        }

        const ull* hb = hbuf + kbase;

        for (int s = 0; s < S_LEN; s++) {
            // non-blocking flag probe for s+1 (checked only after reduce)
            int fv = 1;
            if (t < 128 && s + 1 < S_LEN) fv = ld_acquire(&g_flag[s + 1]);

            ull a01 = 0, a23 = 0;

            // register half: k = kbase + 0 .. kbase + 19
            #pragma unroll
            for (int p = 0; p < K_REG / 2; p++) {
                const ulonglong2 hv = *(const ulonglong2*)(hb + 2 * p);
                a01 = fma2(wr[4 * p + 0], hv.x, a01);
                a23 = fma2(wr[4 * p + 1], hv.x, a23);
                a01 = fma2(wr[4 * p + 2], hv.y, a01);
                a23 = fma2(wr[4 * p + 3], hv.y, a23);
            }
            // smem half: k = kbase + 20 .. kbase + 31
            #pragma unroll
            for (int m = 0; m < K_SMEM; m += 2) {
                const ulonglong2 hv = *(const ulonglong2*)(hb + K_REG + m);
                const ulonglong2 w0 = sW[(ks * K_SMEM + m) * 64 + jq];
                const ulonglong2 w1 = sW[(ks * K_SMEM + m + 1) * 64 + jq];
                a01 = fma2(w0.x, hv.x, a01);
                a23 = fma2(w0.y, hv.x, a23);
                a01 = fma2(w1.x, hv.y, a01);
                a23 = fma2(w1.y, hv.y, a23);
            }

            part[ks * 128 + 2 * jq]     = a01;
            part[ks * 128 + 2 * jq + 1] = a23;
            __syncthreads();   // (A) partials visible; hbuf reads done

            if (t < 128) {
                ull v = add2(add2(add2(part[0 * 128 + t], part[1 * 128 + t]),
                                  add2(part[2 * 128 + t], part[3 * 128 + t])),
                             add2(add2(part[4 * 128 + t], part[5 * 128 + t]),
                                  add2(part[6 * 128 + t], part[7 * 128 + t])));
                v = add2(v, xcur);
                float vx, vy;
                unpack2(v, vx, vy);
                const float tx = tanhf(vx);
                const float ty = tanhf(vy);
                hbuf[2 * t]     = pack2(tx, tx);
                hbuf[2 * t + 1] = pack2(ty, ty);

                // gated prefetch of x for s+1 (has a full step to complete)
                if (s + 1 < S_LEN) {
                    while (fv == 0) {
                        __nanosleep(64);
                        fv = ld_acquire(&g_flag[s + 1]);
                    }
                    xcur = *(const ull*)
                        &g_xproj[((size_t)(s + 1) * B_SZ + b) * 256 + 2 * t];
                }
            }
            __syncthreads();   // (B) new h visible
        }

        if (t < 128) {
            float vx, vy, wx, wy;
            unpack2(hbuf[2 * t],     vx, vy);
            unpack2(hbuf[2 * t + 1], wx, wy);
            out[(size_t)b * 256 + 2 * t]     = vx;
            out[(size_t)b * 256 + 2 * t + 1] = wx;
        }
    } else {
        // =================== WORKER: x_proj producer =======================
        // smem: xs [8][256] f32 (8 KB) + part [8 ks][8 r][256] f32 (64 KB)
        float*  xs     = (float*)smem;
        float*  part_f = (float*)smem + 8 * 256;
        float4* part4  = (float4*)part_f;

        const int w    = blockIdx.x - B_SZ;
        const int jg   = t & 63;       // 4 cols
        const int ks   = t >> 6;       // 8-way k-split, 32 k each
        const int col  = t & 255;
        const int half = t >> 8;       // rows {half, half+2, half+4, half+6}
        const float4* W4 = (const float4*)Wih;
        const float bj = bias[col];

        for (int s = w; s < S_LEN; s += NWORK) {
            #pragma unroll 1
            for (int c = 0; c < 8; c++) {          // 8 chunks of 8 batch rows
                __syncthreads();                   // xs/part reuse safe
                {
                    const float4* srow =
                        (const float4*)(sent + ((size_t)s * 64 + c * 8) * 256);
                    ((float4*)xs)[t] = srow[t];    // 512 float4 = 8 rows
                }
                __syncthreads();

                float4 acc[8];
                #pragma unroll
                for (int r = 0; r < 8; r++) acc[r] = make_float4(0.f, 0.f, 0.f, 0.f);

                #pragma unroll 4
                for (int i = 0; i < 32; i++) {
                    const int k = ks * 32 + i;
                    const float4 wv = W4[k * 64 + jg];
                    #pragma unroll
                    for (int r = 0; r < 8; r++) {
                        const float xv = xs[r * 256 + k];
                        acc[r].x += xv * wv.x;
                        acc[r].y += xv * wv.y;
                        acc[r].z += xv * wv.z;
                        acc[r].w += xv * wv.w;
                    }
                }

                #pragma unroll
                for (int r = 0; r < 8; r++)
                    part4[(ks * 8 + r) * 64 + jg] = acc[r];
                __syncthreads();

                // reduce: thread -> (col, 4 rows)
                #pragma unroll
                for (int rr = 0; rr < 4; rr++) {
                    const int r = half + 2 * rr;
                    float v = bj;
                    #pragma unroll
                    for (int q = 0; q < 8; q++)
                        v += part_f[(q * 8 + r) * 256 + col];
                    g_xproj[((size_t)s * 64 + c * 8 + r) * 256 + col] = v;
                }
            }
            __threadfence();          // x_proj[s] visible gpu-wide
            __syncthreads();          // all threads of worker done with s
            if (t == 0) st_release(&g_flag[s], 1);
        }
    }
}

// ---------------------------------------------------------------------------
extern "C" void kernel_launch(void* const* d_in, const int* in_sizes, int n_in,
                              void* d_out, int out_size)
{
    const float* sentence = (const float*)d_in[0];
    const float* h0       = (const float*)d_in[1];
    const float* W_ih     = (const float*)d_in[2];
    const float* W_hh     = (const float*)d_in[3];
    const float* bias     = (const float*)d_in[4];
    float* out = (float*)d_out;

    (void)in_sizes; (void)n_in; (void)out_size;

    zero_flags<<<(S_LEN + 511) / 512, 512>>>();

    // smem: sW 96KB + part 8KB + hbuf 2KB = 106 KB (covers worker's 72 KB)
    const int smem_bytes = (8 * K_SMEM * 64) * 16 + (8 * 128) * 8 + 256 * 8;
    cudaFuncSetAttribute(fused_kernel,
                         cudaFuncAttributeMaxDynamicSharedMemorySize,
                         smem_bytes);
    fused_kernel<<<B_SZ + NWORK, 512, smem_bytes>>>(
        sentence, W_ih, bias, W_hh, h0, out);
}